// round 10
// baseline (speedup 1.0000x reference)
#include <cuda_runtime.h>
#include <cuda_bf16.h>
#include <math.h>
#include <stdint.h>

#define BB   8
#define NP   16
#define DD   256
#define TL   500
#define SPK  2000
#define SPK_PAD 2048
#define MROWS 8064
#define MT 64
#define NC 64
#define NCHUNK 16
#define LOG2E 1.4426950408889634f
#define LN2   0.6931471805599453f

#define RSA 72                      // A smem row stride (t cols, bf16): 144 B
#define RS  264                     // B smem row stride (k cols, bf16): 528 B
#define SM_A   0                    // 256*72*2 = 36864
#define SM_B0  36864                // 64*264*2 = 33792
#define SM_B1  70656
#define SM_TOTAL 104448

#define PRO_BLOCKS 272              // (2048 Ehi/Esq + 128 E_S out) warps / 8
#define HHI_BLOCKS 504              // 256*4032 bf16x2 pairs / (256 thr * 8)
#define DMIN_BLOCKS 500             // 4000 (b,t) warps / 8

// ---------------- device globals ----------------
__device__ float  g_Esq[SPK_PAD];
__device__ float  g_Hsq[MROWS];
__device__ float  g_pm[4 * MROWS];  // 2 halves x 2 col-groups
__device__ float  g_pl[4 * MROWS];
__device__ double g_dmin_part[DMIN_BLOCKS];
__device__ __nv_bfloat16 g_Ehi[SPK_PAD * DD];
__device__ __nv_bfloat16 g_Hhi[DD * MROWS];   // [k][m], m padded

// ---------------- helpers ----------------
__device__ __forceinline__ uint32_t smem_u32(const void* p) {
    uint32_t a;
    asm("{ .reg .u64 t; cvta.to.shared.u64 t, %1; cvt.u32.u64 %0, t; }" : "=r"(a) : "l"(p));
    return a;
}
__device__ __forceinline__ float ex2(float x) {
    float y; asm("ex2.approx.f32 %0, %1;" : "=f"(y) : "f"(x)); return y;
}
__device__ __forceinline__ void ldm4(uint32_t& r0, uint32_t& r1, uint32_t& r2,
                                     uint32_t& r3, uint32_t a) {
    asm volatile("ldmatrix.sync.aligned.m8n8.x4.shared.b16 {%0,%1,%2,%3}, [%4];"
                 : "=r"(r0), "=r"(r1), "=r"(r2), "=r"(r3) : "r"(a));
}
__device__ __forceinline__ void ldm4t(uint32_t& r0, uint32_t& r1, uint32_t& r2,
                                      uint32_t& r3, uint32_t a) {
    asm volatile("ldmatrix.sync.aligned.m8n8.x4.trans.shared.b16 {%0,%1,%2,%3}, [%4];"
                 : "=r"(r0), "=r"(r1), "=r"(r2), "=r"(r3) : "r"(a));
}
__device__ __forceinline__ void mma16816(float* c, uint32_t a0, uint32_t a1,
                                         uint32_t a2, uint32_t a3,
                                         uint32_t b0, uint32_t b1) {
    asm volatile("mma.sync.aligned.m16n8k16.row.col.f32.bf16.bf16.f32 "
                 "{%0,%1,%2,%3}, {%4,%5,%6,%7}, {%8,%9}, {%0,%1,%2,%3};"
                 : "+f"(c[0]), "+f"(c[1]), "+f"(c[2]), "+f"(c[3])
                 : "r"(a0), "r"(a1), "r"(a2), "r"(a3), "r"(b0), "r"(b1));
}
__device__ __forceinline__ void cp16(uint32_t dst, const void* src) {
    asm volatile("cp.async.cg.shared.global [%0], [%1], 16;" :: "r"(dst), "l"(src));
}
#define CP_COMMIT() asm volatile("cp.async.commit_group;" ::: "memory")
#define CP_WAIT(N)  asm volatile("cp.async.wait_group %0;" :: "n"(N) : "memory")

// ---- int64-vs-int32 sniff for S ----
__device__ __forceinline__ bool s_is_64(const void* Sv) {
    const long long* S = (const long long*)Sv;
    bool ok = true;
#pragma unroll
    for (int i = 0; i < 8; ++i) { long long v = S[i]; if (v < 0 || v >= (long long)SPK) ok = false; }
    return ok;
}
__device__ __forceinline__ long long load_sid(const void* Sv, int idx, bool is64) {
    if (is64) return ((const long long*)Sv)[idx];
    return (long long)((const int*)Sv)[idx];
}

// ---------------------------------------------------------------------------
// pre: [0,PRO): Ehi + Esq + E_S out.  [PRO, PRO+HHI): Hhi bf16 transpose.
//      [PRO+HHI, +DMIN): dmin + Hsq, warp per (b,t).
// ---------------------------------------------------------------------------
__global__ void __launch_bounds__(256)
pre_kernel(const float* __restrict__ H, const void* __restrict__ Sv,
           const float* __restrict__ E, const float* __restrict__ alpha_p,
           const float* __restrict__ beta_p, float* __restrict__ out) {
    int wid = threadIdx.x >> 5, lane = threadIdx.x & 31;

    if (blockIdx.x < PRO_BLOCKS) {
        int gw = blockIdx.x * 8 + wid;
        if (gw < SPK_PAD) {
            int s = gw;
            __nv_bfloat16* eh = g_Ehi + (size_t)s * DD;
            if (s < SPK) {
                const float* e = E + (size_t)s * DD;
                float a = 0.f;
#pragma unroll
                for (int i = 0; i < 8; ++i) {
                    float v = e[lane + i * 32];
                    a = fmaf(v, v, a);
                    eh[lane + i * 32] = __float2bfloat16(v);
                }
#pragma unroll
                for (int off = 16; off > 0; off >>= 1) a += __shfl_xor_sync(0xFFFFFFFFu, a, off);
                if (lane == 0) g_Esq[s] = a;
            } else {
#pragma unroll
                for (int i = 0; i < 8; ++i) eh[lane + i * 32] = __float2bfloat16(0.f);
                if (lane == 0) g_Esq[s] = 1e30f;
            }
        } else if (gw < SPK_PAD + 128) {
            bool is64 = s_is_64(Sv);
            int idx = (gw - SPK_PAD) * 32 + lane;   // < 4096
            int pn = idx >> 8, d = idx & 255;
            long long s = load_sid(Sv, pn * TL, is64);
            out[idx] = E[(size_t)s * DD + d];
        }
        return;
    }

    if (blockIdx.x < PRO_BLOCKS + HHI_BLOCKS) {
        // ---- Hhi: bf16 [k][m] transpose, 8 bf16x2 pairs per thread ----
        int base = (blockIdx.x - PRO_BLOCKS) * 2048 + threadIdx.x;
        uint32_t* dst = (uint32_t*)g_Hhi;
#pragma unroll
        for (int i = 0; i < 8; ++i) {
            int flat = base + i * 256;              // < 256*4032
            int k = flat / 4032, mp = flat - k * 4032;
            int m0 = mp * 2, m1 = m0 + 1;
            float x0 = 0.f, x1 = 0.f;
            if (m0 < NP * TL) {
                int p = m0 / TL, t = m0 - p * TL;
                x0 = H[((size_t)p * DD + k) * TL + t];
            }
            if (m1 < NP * TL) {
                int p = m1 / TL, t = m1 - p * TL;
                x1 = H[((size_t)p * DD + k) * TL + t];
            }
            __nv_bfloat16 h0 = __float2bfloat16(x0), h1 = __float2bfloat16(x1);
            dst[k * 4032 + mp] = (uint32_t)__bfloat16_as_ushort(h0) |
                                 ((uint32_t)__bfloat16_as_ushort(h1) << 16);
        }
        return;
    }

    // ---- dmin + Hsq: warp per (b,t) ----
    __shared__ double warr[8];
    int bd = blockIdx.x - PRO_BLOCKS - HHI_BLOCKS;
    int gw = bd * 8 + wid;                  // < 4000
    double val = 0.0;
    if (gw < BB * TL) {
        bool is64 = s_is_64(Sv);
        int b = gw / TL, t = gw % TL;
        long long sv0 = load_sid(Sv, (b * 2 + 0) * TL + t, is64);
        long long sv1 = load_sid(Sv, (b * 2 + 1) * TL + t, is64);
        const float* h0 = H + (size_t)(b * 2 + 0) * DD * TL + t;
        const float* h1 = H + (size_t)(b * 2 + 1) * DD * TL + t;
        const float* e0 = E + (size_t)sv0 * DD;
        const float* e1 = E + (size_t)sv1 * DD;
        float a00 = 0.f, a01 = 0.f, a10 = 0.f, a11 = 0.f;
        float hs0 = 0.f, hs1 = 0.f;
#pragma unroll
        for (int i = 0; i < 8; ++i) {
            int d = lane + i * 32;
            float x0 = h0[(size_t)d * TL], x1 = h1[(size_t)d * TL];
            float y0 = e0[d], y1 = e1[d];
            hs0 = fmaf(x0, x0, hs0);
            hs1 = fmaf(x1, x1, hs1);
            float u;
            u = x0 - y0; a00 = fmaf(u, u, a00);
            u = x0 - y1; a01 = fmaf(u, u, a01);
            u = x1 - y0; a10 = fmaf(u, u, a10);
            u = x1 - y1; a11 = fmaf(u, u, a11);
        }
#pragma unroll
        for (int off = 16; off > 0; off >>= 1) {
            a00 += __shfl_xor_sync(0xFFFFFFFFu, a00, off);
            a01 += __shfl_xor_sync(0xFFFFFFFFu, a01, off);
            a10 += __shfl_xor_sync(0xFFFFFFFFu, a10, off);
            a11 += __shfl_xor_sync(0xFFFFFFFFu, a11, off);
            hs0 += __shfl_xor_sync(0xFFFFFFFFu, hs0, off);
            hs1 += __shfl_xor_sync(0xFFFFFFFFu, hs1, off);
        }
        if (lane == 0) {
            g_Hsq[(b * 2 + 0) * TL + t] = hs0;
            g_Hsq[(b * 2 + 1) * TL + t] = hs1;
            float dmin = fminf(a00 + a11, a01 + a10);
            val = (double)fmaf(-alpha_p[0], dmin, beta_p[0]);
        }
    }
    if (lane == 0) warr[wid] = val;
    __syncthreads();
    if (threadIdx.x == 0) {
        double s = 0.0;
#pragma unroll
        for (int w = 0; w < 8; ++w) s += warr[w];
        g_dmin_part[bd] = s;
    }
}

// ---------------------------------------------------------------------------
// mma.sync GEMM + online LSE. grid (126, 2), 256 threads = 8 warps, 2 CTA/SM.
// Warp tile 16 rows x 32 cols; chunk = 64 speakers (16 chunks per half).
// Register-pipelined ldmatrix (double-buffered fragments).
// ---------------------------------------------------------------------------
__global__ void __launch_bounds__(256, 2)
gemm_lse_kernel(const float* __restrict__ alpha_p, const float* __restrict__ beta_p) {
    extern __shared__ char smem[];
    uint32_t sb = smem_u32(smem);
    int tid = threadIdx.x;
    int lane = tid & 31, wid = tid >> 5;
    int bx = blockIdx.x;
    int half = blockIdx.y;
    int sbase = half * 1024;
    int t0 = bx * MT;

    const float alpha = alpha_p[0];
    const float a2l = 2.f * alpha * LOG2E;
    const float al  = alpha * LOG2E;

    // ---- prefetch B chunk 0 (group 1) ----
#pragma unroll
    for (int i = 0; i < 8; ++i) {
        int idx = tid + i * 256;            // 2048 16B units (64 spk x 32)
        int s = idx >> 5, u = idx & 31;
        cp16(sb + SM_B0 + (uint32_t)(s * (RS * 2) + u * 16),
             g_Ehi + (size_t)(sbase + s) * DD + u * 8);
    }
    CP_COMMIT();

    // ---- A tile via cp.async from g_Hhi (group 2): 256 k x 64 t ----
#pragma unroll
    for (int i = 0; i < 8; ++i) {
        int idx = tid + i * 256;            // 2048 units: 256 k x 8
        int k = idx >> 3, u = idx & 7;
        cp16(sb + SM_A + (uint32_t)(k * (RSA * 2) + u * 16),
             g_Hhi + (size_t)k * MROWS + t0 + u * 8);
    }
    CP_COMMIT();

    // ---- fragment smem offsets ----
    int r = lane & 7, seg = lane >> 3;
    int cg = wid >> 2;                       // col group: 0 -> cols 0-31, 1 -> 32-63
    int rw = (wid & 3) * 16;                 // warp row base
    uint32_t a_base = (uint32_t)(((seg >> 1) * 8 + r) * RSA + rw + (seg & 1) * 8) * 2;
    uint32_t b_base[2];
#pragma unroll
    for (int p = 0; p < 2; ++p)
        b_base[p] = (uint32_t)((cg * 32 + p * 16 + (seg >> 1) * 8 + r) * RS + (seg & 1) * 8) * 2;

    float mrun[2] = {-1e30f, -1e30f};
    float lrun[2] = {0.f, 0.f};

    for (int c = 0; c < NCHUNK; ++c) {
        int s0 = sbase + c * NC;
        if (c + 1 < NCHUNK) {
            uint32_t bb = ((c + 1) & 1) ? SM_B1 : SM_B0;
            int ns = s0 + NC;
#pragma unroll
            for (int i = 0; i < 8; ++i) {
                int idx = tid + i * 256;
                int s = idx >> 5, u = idx & 31;
                cp16(sb + bb + (uint32_t)(s * (RS * 2) + u * 16),
                     g_Ehi + (size_t)(ns + s) * DD + u * 8);
            }
            CP_COMMIT();
            CP_WAIT(1);                      // current chunk (and A) resident
        } else {
            CP_WAIT(0);
        }
        __syncthreads();

        uint32_t bcur = sb + ((c & 1) ? SM_B1 : SM_B0);

        float acc[4][4];
#pragma unroll
        for (int n = 0; n < 4; ++n)
#pragma unroll
            for (int q = 0; q < 4; ++q) acc[n][q] = 0.f;

        // ---- register-pipelined mainloop: prefetch ks+1 frags during ks ----
        uint32_t af[2][4], bf[2][8];
        ldm4t(af[0][0], af[0][1], af[0][2], af[0][3], sb + SM_A + a_base);
        ldm4(bf[0][0], bf[0][1], bf[0][2], bf[0][3], bcur + b_base[0]);
        ldm4(bf[0][4], bf[0][5], bf[0][6], bf[0][7], bcur + b_base[1]);
#pragma unroll
        for (int ks = 0; ks < 16; ++ks) {
            int cu = ks & 1, nx = cu ^ 1;
            if (ks < 15) {
                uint32_t ka = (uint32_t)(ks + 1);
                ldm4t(af[nx][0], af[nx][1], af[nx][2], af[nx][3],
                      sb + SM_A + a_base + ka * (16 * RSA * 2));
                ldm4(bf[nx][0], bf[nx][1], bf[nx][2], bf[nx][3],
                     bcur + b_base[0] + ka * 32);
                ldm4(bf[nx][4], bf[nx][5], bf[nx][6], bf[nx][7],
                     bcur + b_base[1] + ka * 32);
            }
            mma16816(acc[0], af[cu][0], af[cu][1], af[cu][2], af[cu][3], bf[cu][0], bf[cu][1]);
            mma16816(acc[1], af[cu][0], af[cu][1], af[cu][2], af[cu][3], bf[cu][2], bf[cu][3]);
            mma16816(acc[2], af[cu][0], af[cu][1], af[cu][2], af[cu][3], bf[cu][4], bf[cu][5]);
            mma16816(acc[3], af[cu][0], af[cu][1], af[cu][2], af[cu][3], bf[cu][6], bf[cu][7]);
        }

        // ---- epilogue: online LSE (log2 domain) ----
        int qn = (lane & 3) * 2;
        float nml[8];
#pragma unroll
        for (int j = 0; j < 4; ++j) {
            int cj = s0 + cg * 32 + (j >> 1) * 16 + (j & 1) * 8 + qn;
            nml[2 * j]     = -al * g_Esq[cj];
            nml[2 * j + 1] = -al * g_Esq[cj + 1];
        }
#pragma unroll
        for (int h = 0; h < 2; ++h) {
            float v[8], vmax = -1e30f;
#pragma unroll
            for (int j = 0; j < 4; ++j) {
#pragma unroll
                for (int cc = 0; cc < 2; ++cc) {
                    float vv = fmaf(a2l, acc[j][h * 2 + cc], nml[2 * j + cc]);
                    v[2 * j + cc] = vv;
                    vmax = fmaxf(vmax, vv);
                }
            }
            float nm = fmaxf(mrun[h], vmax);
            float e = 0.f;
#pragma unroll
            for (int j = 0; j < 8; ++j) e += ex2(v[j] - nm);
            lrun[h] = fmaf(lrun[h], ex2(mrun[h] - nm), e);
            mrun[h] = nm;
        }
        __syncthreads();   // all warps done reading bcur before refill
    }

    // ---- reduce across 4 lanes sharing each row; write quarter partials ----
    int q = half * 2 + cg;
#pragma unroll
    for (int h = 0; h < 2; ++h) {
#pragma unroll
        for (int off = 1; off <= 2; off <<= 1) {
            float m2 = __shfl_xor_sync(0xFFFFFFFFu, mrun[h], off);
            float l2 = __shfl_xor_sync(0xFFFFFFFFu, lrun[h], off);
            float nm = fmaxf(mrun[h], m2);
            lrun[h] = lrun[h] * ex2(mrun[h] - nm) + l2 * ex2(m2 - nm);
            mrun[h] = nm;
        }
        if ((lane & 3) == 0) {
            int gm = bx * MT + rw + h * 8 + (lane >> 2);
            g_pm[q * MROWS + gm] = mrun[h];
            g_pl[q * MROWS + gm] = lrun[h];
        }
    }
}

// ---------------------------------------------------------------------------
// Single-block merge + finalize.
// ---------------------------------------------------------------------------
__global__ void __launch_bounds__(1024)
merge_kernel(const float* __restrict__ alpha_p, const float* __restrict__ beta_p,
             float* __restrict__ out, int loss_idx) {
    __shared__ double w_lse[32], w_dm[32];
    int tid = threadIdx.x, lane = tid & 31, wid = tid >> 5;
    float alpha = alpha_p[0], beta = beta_p[0];

    double acc = 0.0;
    for (int idx = tid; idx < NP * TL; idx += 1024) {
        float m0 = g_pm[idx],             l0 = g_pl[idx];
        float m1 = g_pm[MROWS + idx],     l1 = g_pl[MROWS + idx];
        float m2 = g_pm[2 * MROWS + idx], l2 = g_pl[2 * MROWS + idx];
        float m3 = g_pm[3 * MROWS + idx], l3 = g_pl[3 * MROWS + idx];
        float M = fmaxf(fmaxf(m0, m1), fmaxf(m2, m3));
        float L = l0 * ex2(m0 - M) + l1 * ex2(m1 - M) +
                  l2 * ex2(m2 - M) + l3 * ex2(m3 - M);
        float lse = (M + log2f(L)) * LN2;
        acc += (double)(lse + fmaf(-alpha, g_Hsq[idx], beta));
    }
    double dm = 0.0;
    if (tid < DMIN_BLOCKS) dm = g_dmin_part[tid];

#pragma unroll
    for (int off = 16; off > 0; off >>= 1) {
        acc += __shfl_down_sync(0xFFFFFFFFu, acc, off);
        dm  += __shfl_down_sync(0xFFFFFFFFu, dm, off);
    }
    if (lane == 0) { w_lse[wid] = acc; w_dm[wid] = dm; }
    __syncthreads();
    if (tid == 0) {
        double sl = 0.0, sd = 0.0;
#pragma unroll
        for (int w = 0; w < 32; ++w) { sl += w_lse[w]; sd += w_dm[w]; }
        out[loss_idx] = (float)(-(sd / (double)(BB * TL)) + (sl / (double)(NP * TL)));
    }
}

// ---------------------------------------------------------------------------
extern "C" void kernel_launch(void* const* d_in, const int* in_sizes, int n_in,
                              void* d_out, int out_size) {
    const float* H     = (const float*)d_in[0];
    const void*  S     = (const void*)d_in[1];
    const float* E     = (const float*)d_in[2];
    const float* alpha = (const float*)d_in[3];
    const float* beta  = (const float*)d_in[4];
    float* out = (float*)d_out;

    cudaFuncSetAttribute(gemm_lse_kernel,
                         cudaFuncAttributeMaxDynamicSharedMemorySize, SM_TOTAL);

    pre_kernel<<<PRO_BLOCKS + HHI_BLOCKS + DMIN_BLOCKS, 256>>>(H, S, E, alpha, beta, out);
    gemm_lse_kernel<<<dim3(126, 2), 256, SM_TOTAL>>>(alpha, beta);
    merge_kernel<<<1, 1024>>>(alpha, beta, out, out_size - 1);
}

// round 11
// speedup vs baseline: 1.0755x; 1.0755x over previous
#include <cuda_runtime.h>
#include <cuda_fp16.h>
#include <math.h>
#include <stdint.h>

#define BB   8
#define NP   16
#define DD   256
#define TL   500
#define SPK  2000
#define SPK_PAD 2048
#define MROWS 8064
#define MT 128
#define NC 128
#define NCHUNK 8
#define LOG2E 1.4426950408889634f
#define LN2   0.6931471805599453f

#define RSA 136                     // A smem row stride (t cols, f16): 272 B
#define RS  264                     // B smem row stride (k cols, f16): 528 B
#define SM_A   0                    // 256*136*2 = 69632
#define SM_B0  69632                // 128*264*2 = 67584
#define SM_B1  137216
#define SM_TOTAL 204800

#define PRO_BLOCKS 272              // (2048 Ehi/Esq + 128 E_S out) warps / 8
#define HHI_BLOCKS 504              // 256*4032 f16x2 pairs / (256 thr * 8)
#define DMIN_BLOCKS 500             // 4000 (b,t) warps / 8

// ---------------- device globals ----------------
__device__ float  g_Esq[SPK_PAD];
__device__ float  g_Hsq[MROWS];
__device__ float  g_pm[4 * MROWS];  // 2 halves x 2 col-groups
__device__ float  g_pl[4 * MROWS];
__device__ double g_dmin_part[DMIN_BLOCKS];
__device__ __half g_Ehi[SPK_PAD * DD];
__device__ __half g_Hhi[DD * MROWS];   // [k][m], m padded

// ---------------- helpers ----------------
__device__ __forceinline__ uint32_t smem_u32(const void* p) {
    uint32_t a;
    asm("{ .reg .u64 t; cvta.to.shared.u64 t, %1; cvt.u32.u64 %0, t; }" : "=r"(a) : "l"(p));
    return a;
}
__device__ __forceinline__ float ex2(float x) {
    float y; asm("ex2.approx.f32 %0, %1;" : "=f"(y) : "f"(x)); return y;
}
__device__ __forceinline__ void ldm4(uint32_t& r0, uint32_t& r1, uint32_t& r2,
                                     uint32_t& r3, uint32_t a) {
    asm volatile("ldmatrix.sync.aligned.m8n8.x4.shared.b16 {%0,%1,%2,%3}, [%4];"
                 : "=r"(r0), "=r"(r1), "=r"(r2), "=r"(r3) : "r"(a));
}
__device__ __forceinline__ void ldm4t(uint32_t& r0, uint32_t& r1, uint32_t& r2,
                                      uint32_t& r3, uint32_t a) {
    asm volatile("ldmatrix.sync.aligned.m8n8.x4.trans.shared.b16 {%0,%1,%2,%3}, [%4];"
                 : "=r"(r0), "=r"(r1), "=r"(r2), "=r"(r3) : "r"(a));
}
// f16 accumulate: C is 2 packed f16x2 regs
__device__ __forceinline__ void mma16816h(uint32_t& c0, uint32_t& c1,
                                          uint32_t a0, uint32_t a1,
                                          uint32_t a2, uint32_t a3,
                                          uint32_t b0, uint32_t b1) {
    asm volatile("mma.sync.aligned.m16n8k16.row.col.f16.f16.f16.f16 "
                 "{%0,%1}, {%2,%3,%4,%5}, {%6,%7}, {%0,%1};"
                 : "+r"(c0), "+r"(c1)
                 : "r"(a0), "r"(a1), "r"(a2), "r"(a3), "r"(b0), "r"(b1));
}
__device__ __forceinline__ void cp16(uint32_t dst, const void* src) {
    asm volatile("cp.async.cg.shared.global [%0], [%1], 16;" :: "r"(dst), "l"(src));
}
#define CP_COMMIT() asm volatile("cp.async.commit_group;" ::: "memory")
#define CP_WAIT(N)  asm volatile("cp.async.wait_group %0;" :: "n"(N) : "memory")

// ---- int64-vs-int32 sniff for S ----
__device__ __forceinline__ bool s_is_64(const void* Sv) {
    const long long* S = (const long long*)Sv;
    bool ok = true;
#pragma unroll
    for (int i = 0; i < 8; ++i) { long long v = S[i]; if (v < 0 || v >= (long long)SPK) ok = false; }
    return ok;
}
__device__ __forceinline__ long long load_sid(const void* Sv, int idx, bool is64) {
    if (is64) return ((const long long*)Sv)[idx];
    return (long long)((const int*)Sv)[idx];
}

// ---------------------------------------------------------------------------
// pre: [0,PRO): Ehi + Esq + E_S out.  [PRO, PRO+HHI): Hhi f16 transpose.
//      [PRO+HHI, +DMIN): dmin + Hsq, warp per (b,t).
// ---------------------------------------------------------------------------
__global__ void __launch_bounds__(256)
pre_kernel(const float* __restrict__ H, const void* __restrict__ Sv,
           const float* __restrict__ E, const float* __restrict__ alpha_p,
           const float* __restrict__ beta_p, float* __restrict__ out) {
    int wid = threadIdx.x >> 5, lane = threadIdx.x & 31;

    if (blockIdx.x < PRO_BLOCKS) {
        int gw = blockIdx.x * 8 + wid;
        if (gw < SPK_PAD) {
            int s = gw;
            __half* eh = g_Ehi + (size_t)s * DD;
            if (s < SPK) {
                const float* e = E + (size_t)s * DD;
                float a = 0.f;
#pragma unroll
                for (int i = 0; i < 8; ++i) {
                    float v = e[lane + i * 32];
                    a = fmaf(v, v, a);
                    eh[lane + i * 32] = __float2half(v);
                }
#pragma unroll
                for (int off = 16; off > 0; off >>= 1) a += __shfl_xor_sync(0xFFFFFFFFu, a, off);
                if (lane == 0) g_Esq[s] = a;
            } else {
#pragma unroll
                for (int i = 0; i < 8; ++i) eh[lane + i * 32] = __float2half(0.f);
                if (lane == 0) g_Esq[s] = 1e30f;
            }
        } else if (gw < SPK_PAD + 128) {
            bool is64 = s_is_64(Sv);
            int idx = (gw - SPK_PAD) * 32 + lane;   // < 4096
            int pn = idx >> 8, d = idx & 255;
            long long s = load_sid(Sv, pn * TL, is64);
            out[idx] = E[(size_t)s * DD + d];
        }
        return;
    }

    if (blockIdx.x < PRO_BLOCKS + HHI_BLOCKS) {
        // ---- Hhi: f16 [k][m] transpose, 8 f16x2 pairs per thread ----
        int base = (blockIdx.x - PRO_BLOCKS) * 2048 + threadIdx.x;
        uint32_t* dst = (uint32_t*)g_Hhi;
#pragma unroll
        for (int i = 0; i < 8; ++i) {
            int flat = base + i * 256;              // < 256*4032
            int k = flat / 4032, mp = flat - k * 4032;
            int m0 = mp * 2, m1 = m0 + 1;
            float x0 = 0.f, x1 = 0.f;
            if (m0 < NP * TL) {
                int p = m0 / TL, t = m0 - p * TL;
                x0 = H[((size_t)p * DD + k) * TL + t];
            }
            if (m1 < NP * TL) {
                int p = m1 / TL, t = m1 - p * TL;
                x1 = H[((size_t)p * DD + k) * TL + t];
            }
            __half h0 = __float2half(x0), h1 = __float2half(x1);
            dst[k * 4032 + mp] = (uint32_t)__half_as_ushort(h0) |
                                 ((uint32_t)__half_as_ushort(h1) << 16);
        }
        return;
    }

    // ---- dmin + Hsq: warp per (b,t) ----
    __shared__ double warr[8];
    int bd = blockIdx.x - PRO_BLOCKS - HHI_BLOCKS;
    int gw = bd * 8 + wid;                  // < 4000
    double val = 0.0;
    if (gw < BB * TL) {
        bool is64 = s_is_64(Sv);
        int b = gw / TL, t = gw % TL;
        long long sv0 = load_sid(Sv, (b * 2 + 0) * TL + t, is64);
        long long sv1 = load_sid(Sv, (b * 2 + 1) * TL + t, is64);
        const float* h0 = H + (size_t)(b * 2 + 0) * DD * TL + t;
        const float* h1 = H + (size_t)(b * 2 + 1) * DD * TL + t;
        const float* e0 = E + (size_t)sv0 * DD;
        const float* e1 = E + (size_t)sv1 * DD;
        float a00 = 0.f, a01 = 0.f, a10 = 0.f, a11 = 0.f;
        float hs0 = 0.f, hs1 = 0.f;
#pragma unroll
        for (int i = 0; i < 8; ++i) {
            int d = lane + i * 32;
            float x0 = h0[(size_t)d * TL], x1 = h1[(size_t)d * TL];
            float y0 = e0[d], y1 = e1[d];
            hs0 = fmaf(x0, x0, hs0);
            hs1 = fmaf(x1, x1, hs1);
            float u;
            u = x0 - y0; a00 = fmaf(u, u, a00);
            u = x0 - y1; a01 = fmaf(u, u, a01);
            u = x1 - y0; a10 = fmaf(u, u, a10);
            u = x1 - y1; a11 = fmaf(u, u, a11);
        }
#pragma unroll
        for (int off = 16; off > 0; off >>= 1) {
            a00 += __shfl_xor_sync(0xFFFFFFFFu, a00, off);
            a01 += __shfl_xor_sync(0xFFFFFFFFu, a01, off);
            a10 += __shfl_xor_sync(0xFFFFFFFFu, a10, off);
            a11 += __shfl_xor_sync(0xFFFFFFFFu, a11, off);
            hs0 += __shfl_xor_sync(0xFFFFFFFFu, hs0, off);
            hs1 += __shfl_xor_sync(0xFFFFFFFFu, hs1, off);
        }
        if (lane == 0) {
            g_Hsq[(b * 2 + 0) * TL + t] = hs0;
            g_Hsq[(b * 2 + 1) * TL + t] = hs1;
            float dmin = fminf(a00 + a11, a01 + a10);
            val = (double)fmaf(-alpha_p[0], dmin, beta_p[0]);
        }
    }
    if (lane == 0) warr[wid] = val;
    __syncthreads();
    if (threadIdx.x == 0) {
        double s = 0.0;
#pragma unroll
        for (int w = 0; w < 8; ++w) s += warr[w];
        g_dmin_part[bd] = s;
    }
}

// ---------------------------------------------------------------------------
// mma.sync GEMM (f16 accum) + online LSE. grid (63, 2), 512 threads = 16 warps.
// Warp tile 16 rows x 64 cols; chunk = 128 speakers (8 chunks per half).
// ---------------------------------------------------------------------------
__global__ void __launch_bounds__(512, 1)
gemm_lse_kernel(const float* __restrict__ alpha_p, const float* __restrict__ beta_p) {
    extern __shared__ char smem[];
    uint32_t sb = smem_u32(smem);
    int tid = threadIdx.x;
    int lane = tid & 31, wid = tid >> 5;
    int bx = blockIdx.x;
    int half = blockIdx.y;
    int sbase = half * 1024;
    int t0 = bx * MT;

    const float alpha = alpha_p[0];
    const float a2l = 2.f * alpha * LOG2E;
    const float al  = alpha * LOG2E;

    // ---- prefetch B chunk 0 (group 1) ----
#pragma unroll
    for (int i = 0; i < 8; ++i) {
        int idx = tid + i * 512;            // 4096 16B units (128 spk x 32)
        int s = idx >> 5, u = idx & 31;
        cp16(sb + SM_B0 + (uint32_t)(s * (RS * 2) + u * 16),
             g_Ehi + (size_t)(sbase + s) * DD + u * 8);
    }
    CP_COMMIT();

    // ---- A tile via cp.async from g_Hhi (group 2) ----
#pragma unroll
    for (int i = 0; i < 8; ++i) {
        int idx = tid + i * 512;            // 4096 units: 256 k x 16
        int k = idx >> 4, u = idx & 15;
        cp16(sb + SM_A + (uint32_t)(k * (RSA * 2) + u * 16),
             g_Hhi + (size_t)k * MROWS + t0 + u * 8);
    }
    CP_COMMIT();

    // ---- fragment smem offsets ----
    int r = lane & 7, seg = lane >> 3;
    int cg = wid >> 3;                       // col group: 0 -> cols 0-63, 1 -> 64-127
    int rw = (wid & 7) * 16;                 // warp row base
    uint32_t a_base = (uint32_t)(((seg >> 1) * 8 + r) * RSA + rw + (seg & 1) * 8) * 2;
    uint32_t b_base[4];
#pragma unroll
    for (int p = 0; p < 4; ++p)
        b_base[p] = (uint32_t)((cg * 64 + p * 16 + (seg >> 1) * 8 + r) * RS + (seg & 1) * 8) * 2;

    float mrun[2] = {-1e30f, -1e30f};
    float lrun[2] = {0.f, 0.f};

    for (int c = 0; c < NCHUNK; ++c) {
        int s0 = sbase + c * NC;
        if (c + 1 < NCHUNK) {
            uint32_t bb = ((c + 1) & 1) ? SM_B1 : SM_B0;
            int ns = s0 + NC;
#pragma unroll
            for (int i = 0; i < 8; ++i) {
                int idx = tid + i * 512;
                int s = idx >> 5, u = idx & 31;
                cp16(sb + bb + (uint32_t)(s * (RS * 2) + u * 16),
                     g_Ehi + (size_t)(ns + s) * DD + u * 8);
            }
            CP_COMMIT();
            CP_WAIT(1);                      // current chunk (and A) resident
        } else {
            CP_WAIT(0);
        }
        __syncthreads();

        uint32_t bcur = sb + ((c & 1) ? SM_B1 : SM_B0);

        uint32_t acc[8][2];                  // f16x2 accumulators
#pragma unroll
        for (int n = 0; n < 8; ++n) { acc[n][0] = 0u; acc[n][1] = 0u; }

#pragma unroll 4
        for (int ks = 0; ks < 16; ++ks) {
            uint32_t a0, a1, a2, a3;
            ldm4t(a0, a1, a2, a3, sb + SM_A + a_base + (uint32_t)ks * (16 * RSA * 2));
#pragma unroll
            for (int p = 0; p < 4; ++p) {
                uint32_t b0, b1, b2, b3;
                ldm4(b0, b1, b2, b3, bcur + b_base[p] + (uint32_t)ks * 32);
                mma16816h(acc[2 * p][0],     acc[2 * p][1],     a0, a1, a2, a3, b0, b1);
                mma16816h(acc[2 * p + 1][0], acc[2 * p + 1][1], a0, a1, a2, a3, b2, b3);
            }
        }

        // ---- epilogue: online LSE (log2 domain) ----
        int qn = (lane & 3) * 2;
        float nml[16];
#pragma unroll
        for (int j = 0; j < 8; ++j) {
            int cj = s0 + cg * 64 + (j >> 1) * 16 + (j & 1) * 8 + qn;
            nml[2 * j]     = -al * g_Esq[cj];
            nml[2 * j + 1] = -al * g_Esq[cj + 1];
        }
#pragma unroll
        for (int h = 0; h < 2; ++h) {
            float v[16], vmax = -1e30f;
#pragma unroll
            for (int j = 0; j < 8; ++j) {
                float2 d2 = __half22float2(*(__half2*)&acc[j][h]);
                float v0 = fmaf(a2l, d2.x, nml[2 * j]);
                float v1 = fmaf(a2l, d2.y, nml[2 * j + 1]);
                v[2 * j] = v0; v[2 * j + 1] = v1;
                vmax = fmaxf(vmax, fmaxf(v0, v1));
            }
            float nm = fmaxf(mrun[h], vmax);
            float e = 0.f;
#pragma unroll
            for (int j = 0; j < 16; ++j) e += ex2(v[j] - nm);
            lrun[h] = fmaf(lrun[h], ex2(mrun[h] - nm), e);
            mrun[h] = nm;
        }
        __syncthreads();   // all warps done reading bcur before refill
    }

    // ---- reduce across 4 lanes sharing each row; write quarter partials ----
    int q = half * 2 + cg;
#pragma unroll
    for (int h = 0; h < 2; ++h) {
#pragma unroll
        for (int off = 1; off <= 2; off <<= 1) {
            float m2 = __shfl_xor_sync(0xFFFFFFFFu, mrun[h], off);
            float l2 = __shfl_xor_sync(0xFFFFFFFFu, lrun[h], off);
            float nm = fmaxf(mrun[h], m2);
            lrun[h] = lrun[h] * ex2(mrun[h] - nm) + l2 * ex2(m2 - nm);
            mrun[h] = nm;
        }
        if ((lane & 3) == 0) {
            int gm = bx * MT + rw + h * 8 + (lane >> 2);
            g_pm[q * MROWS + gm] = mrun[h];
            g_pl[q * MROWS + gm] = lrun[h];
        }
    }
}

// ---------------------------------------------------------------------------
// Single-block merge + finalize.
// ---------------------------------------------------------------------------
__global__ void __launch_bounds__(1024)
merge_kernel(const float* __restrict__ alpha_p, const float* __restrict__ beta_p,
             float* __restrict__ out, int loss_idx) {
    __shared__ double w_lse[32], w_dm[32];
    int tid = threadIdx.x, lane = tid & 31, wid = tid >> 5;
    float alpha = alpha_p[0], beta = beta_p[0];

    double acc = 0.0;
    for (int idx = tid; idx < NP * TL; idx += 1024) {
        float m0 = g_pm[idx],             l0 = g_pl[idx];
        float m1 = g_pm[MROWS + idx],     l1 = g_pl[MROWS + idx];
        float m2 = g_pm[2 * MROWS + idx], l2 = g_pl[2 * MROWS + idx];
        float m3 = g_pm[3 * MROWS + idx], l3 = g_pl[3 * MROWS + idx];
        float M = fmaxf(fmaxf(m0, m1), fmaxf(m2, m3));
        float L = l0 * ex2(m0 - M) + l1 * ex2(m1 - M) +
                  l2 * ex2(m2 - M) + l3 * ex2(m3 - M);
        float lse = (M + log2f(L)) * LN2;
        acc += (double)(lse + fmaf(-alpha, g_Hsq[idx], beta));
    }
    double dm = 0.0;
    if (tid < DMIN_BLOCKS) dm = g_dmin_part[tid];

#pragma unroll
    for (int off = 16; off > 0; off >>= 1) {
        acc += __shfl_down_sync(0xFFFFFFFFu, acc, off);
        dm  += __shfl_down_sync(0xFFFFFFFFu, dm, off);
    }
    if (lane == 0) { w_lse[wid] = acc; w_dm[wid] = dm; }
    __syncthreads();
    if (tid == 0) {
        double sl = 0.0, sd = 0.0;
#pragma unroll
        for (int w = 0; w < 32; ++w) { sl += w_lse[w]; sd += w_dm[w]; }
        out[loss_idx] = (float)(-(sd / (double)(BB * TL)) + (sl / (double)(NP * TL)));
    }
}

// ---------------------------------------------------------------------------
extern "C" void kernel_launch(void* const* d_in, const int* in_sizes, int n_in,
                              void* d_out, int out_size) {
    const float* H     = (const float*)d_in[0];
    const void*  S     = (const void*)d_in[1];
    const float* E     = (const float*)d_in[2];
    const float* alpha = (const float*)d_in[3];
    const float* beta  = (const float*)d_in[4];
    float* out = (float*)d_out;

    cudaFuncSetAttribute(gemm_lse_kernel,
                         cudaFuncAttributeMaxDynamicSharedMemorySize, SM_TOTAL);

    pre_kernel<<<PRO_BLOCKS + HHI_BLOCKS + DMIN_BLOCKS, 256>>>(H, S, E, alpha, beta, out);
    gemm_lse_kernel<<<dim3(63, 2), 512, SM_TOTAL>>>(alpha, beta);
    merge_kernel<<<1, 1024>>>(alpha, beta, out, out_size - 1);
}